// round 8
// baseline (speedup 1.0000x reference)
#include <cuda_runtime.h>
#include <cuda_fp16.h>
#include <math.h>

// ---------------------------------------------------------------------------
// ControllerLSTM on GB300, round 6.
// Kept: batch collapse (B=1), fused fp16 [W_ih|W_hh] (L2-resident), warp-
// specialized persistent kernel, flag grid barrier.
// New: (1) conflict-free smem x via even/odd float4 split arrays (lane
// stride 16B -> no bank conflicts), (2) grid 148 x 896 threads: all SMs,
// per-SM weight slice 448KB (was 512KB), regs headroom 73, (3) ih warps
// stage the chosen embedding themselves (no idx broadcast to hh warps).
// ---------------------------------------------------------------------------

#define H    2048
#define H2X  4096
#define H4   512          // float4 count of H
#define BSZ  1024
#define NBK  12
#define NCOL 2048

#define NCTA  148
#define NTHR  896
#define NPAIR 14          // warp pairs per CTA (ih wid 0..13, hh wid 14..27)

__device__ __half g_wc[(size_t)4 * H * H2X];   // 67.1 MB fused fp16 weights
__device__ float  g_hbuf[2][H];
__device__ float  g_cbuf[H];

#define FLAG_STRIDE 8
__device__ volatile unsigned g_arrive[NCTA * FLAG_STRIDE];
__device__ volatile unsigned g_release;

__device__ __forceinline__ void grid_sync_flags(unsigned gen) {
    __syncthreads();
    const int tid = threadIdx.x;
    if (blockIdx.x == 0) {
        if (tid == 0) { __threadfence(); g_arrive[0] = gen; }
        if (tid < NCTA) {
            while (g_arrive[tid * FLAG_STRIDE] != gen) { }
        }
        __syncthreads();
        if (tid == 0) { __threadfence(); g_release = gen; }
    } else {
        if (tid == 0) {
            __threadfence();
            g_arrive[blockIdx.x * FLAG_STRIDE] = gen;
            while (g_release != gen) { }
        }
    }
    __syncthreads();
}

__device__ __forceinline__ float wred(float v) {
    #pragma unroll
    for (int o = 16; o > 0; o >>= 1) v += __shfl_xor_sync(0xffffffffu, v, o);
    return v;
}

__device__ __forceinline__ float sigf(float x) { return 1.0f / (1.0f + expf(-x)); }

__device__ __forceinline__ float dot8(uint4 w, float4 xa, float4 xb) {
    union { unsigned u; __half2 h; } c0, c1, c2, c3;
    c0.u = w.x; c1.u = w.y; c2.u = w.z; c3.u = w.w;
    const float2 f0 = __half22float2(c0.h);
    const float2 f1 = __half22float2(c1.h);
    const float2 f2 = __half22float2(c2.h);
    const float2 f3 = __half22float2(c3.h);
    return f0.x*xa.x + f0.y*xa.y + f1.x*xa.z + f1.y*xa.w
         + f2.x*xb.x + f2.y*xb.y + f3.x*xb.z + f3.y*xb.w;
}

#define IH_BAR() asm volatile("bar.sync 1, 448;" ::: "memory")

// decode params for hidden state produced by cell s
__device__ __forceinline__ void dec_params(int s, const float* dec_act,
                                           const float* dec_block,
                                           const float** dec, int* ncls) {
    if (s == 0) { *dec = dec_act; *ncls = 4; }
    else if (s & 1) { int bid = (s + 1) >> 1; *dec = dec_block + (size_t)(bid - 1) * (NBK - 1) * H; *ncls = bid; }
    else            { int bid = s >> 1;       *dec = dec_act   + (size_t)bid * 4 * H;               *ncls = 4; }
}

// ===========================================================================
// Kernel 0: fused fp16 conversion (k<2048 = W_ih row, k>=2048 = W_hh row).
// ===========================================================================
__global__ __launch_bounds__(256, 2)
void convert_weights(const float* __restrict__ W_ih, const float* __restrict__ W_hh)
{
    const size_t n = (size_t)4 * H * H2X / 8;
    const size_t stride = (size_t)gridDim.x * blockDim.x;
    uint4* __restrict__ dst = (uint4*)g_wc;
    for (size_t i = blockIdx.x * blockDim.x + threadIdx.x; i < n; i += stride) {
        const size_t o   = i * 8;
        const size_t row = o >> 12;
        const size_t k0  = o & 4095;
        const float* src = (k0 < H) ? (W_ih + row * H + k0) : (W_hh + row * H + (k0 - H));
        const float4 v0 = *(const float4*)src;
        const float4 v1 = *(const float4*)(src + 4);
        union { __half2 h; unsigned u; } a, b, c, d;
        a.h = __floats2half2_rn(v0.x, v0.y);
        b.h = __floats2half2_rn(v0.z, v0.w);
        c.h = __floats2half2_rn(v1.x, v1.y);
        d.h = __floats2half2_rn(v1.z, v1.w);
        dst[i] = make_uint4(a.u, b.u, c.u, d.u);
    }
}

// ===========================================================================
// Kernel 1: persistent controller, warp-specialized, split-array smem.
// ===========================================================================
__global__ __launch_bounds__(NTHR, 1)
void controller_main(const float* __restrict__ b_ih,
                     const float* __restrict__ b_hh,
                     const float* __restrict__ enc_act,
                     const float* __restrict__ enc_block,
                     const float* __restrict__ dec_act,
                     const float* __restrict__ dec_block,
                     float* __restrict__ out)
{
    // split even/odd float4 arrays: conflict-free 16B lane stride
    __shared__ float4 hA[256], hB[256];    // h:  hA[j]=h[8j..8j+3], hB[j]=h[8j+4..]
    __shared__ float4 eA[256], eB[256];    // e (and final c in epilogue)
    __shared__ float  dec_sm[NBK - 1];
    __shared__ float  psum_hh[NPAIR][4];
    __shared__ float  psum_p2[NPAIR][4];
    __shared__ int    idx_final;

    const int tid  = threadIdx.x;
    const int lane = tid & 31;
    const int wid  = tid >> 5;
    const bool ih  = (wid < NPAIR);            // threads 0..447
    const int w    = ih ? wid : (wid - NPAIR); // pair slot
    const int gw   = blockIdx.x * NPAIR + w;   // gate column
    const bool valid = (gw < NCOL);
    const int gwc  = valid ? gw : (NCOL - 1);

    float bsum[4];
    #pragma unroll
    for (int g = 0; g < 4; g++) bsum[g] = b_ih[g * H + gwc] + b_hh[g * H + gwc];

    const uint4* wp[4];
    #pragma unroll
    for (int g = 0; g < 4; g++)
        wp[g] = (const uint4*)(g_wc + ((size_t)(g * H + gwc)) * H2X);

    float cloc = 0.f;          // ih lane 0 of each valid pair
    unsigned gen = 0;

    for (int cell = 0; cell < 2 * NBK - 1; cell++) {
        if (cell == 0) {
            if (ih && lane == 0 && valid) {
                const float c2 = sigf(bsum[0]) * tanhf(bsum[2]);
                const float h2 = sigf(bsum[3]) * tanhf(c2);
                cloc = c2;
                g_hbuf[0][gw] = h2;
            }
        } else {
            // ---- stage h_{cell-1} into split arrays ----
            if (tid < H4) {
                const float4 v = __ldcv((const float4*)g_hbuf[(cell - 1) & 1] + tid);
                const int j = tid >> 1;
                if (tid & 1) hB[j] = v; else hA[j] = v;
            }
            __syncthreads();

            if (ih) {
                // ---- decode h_{cell-1}, then stage e_cell (overlaps hh GEMV) ----
                const float* dec; int ncls;
                dec_params(cell - 1, dec_act, dec_block, &dec, &ncls);
                if (w < ncls) {
                    const float4* dr = (const float4*)(dec + (size_t)w * H);
                    float s = 0.f;
                    #pragma unroll 2
                    for (int t2 = lane; t2 < 256; t2 += 32) {
                        const float4 d0 = dr[2 * t2], d1 = dr[2 * t2 + 1];
                        const float4 ha = hA[t2], hb = hB[t2];
                        s += d0.x*ha.x + d0.y*ha.y + d0.z*ha.z + d0.w*ha.w
                           + d1.x*hb.x + d1.y*hb.y + d1.z*hb.z + d1.w*hb.w;
                    }
                    s = wred(s);
                    if (lane == 0) dec_sm[w] = s;
                }
                IH_BAR();
                float best = dec_sm[0]; int bi = 0;
                for (int j = 1; j < ncls; j++) { float v = dec_sm[j]; if (v > best) { best = v; bi = j; } }
                const int bid = (cell + 1) >> 1;
                const float* emb = (cell & 1)
                    ? enc_act   + ((size_t)(bid - 1) * 4         + bi) * H
                    : enc_block + ((size_t)(bid - 1) * (NBK - 1) + bi) * H;
                const float4* ef = (const float4*)emb;
                for (int t = tid; t < H4; t += NPAIR * 32) {
                    const float4 v = __ldg(ef + t);
                    const int j = t >> 1;
                    if (t & 1) eB[j] = v; else eA[j] = v;
                }
            } else {
                // ---- hh GEMV: fused k in [2048,4096) -> jj in [0,256) ----
                float4 acc = make_float4(0.f, 0.f, 0.f, 0.f);
                if (valid) {
                    #pragma unroll 2
                    for (int jj = lane; jj < 256; jj += 32) {
                        const float4 xa = hA[jj], xb = hB[jj];
                        const int j = 256 + jj;
                        acc.x += dot8(wp[0][j], xa, xb);
                        acc.y += dot8(wp[1][j], xa, xb);
                        acc.z += dot8(wp[2][j], xa, xb);
                        acc.w += dot8(wp[3][j], xa, xb);
                    }
                }
                acc.x = wred(acc.x); acc.y = wred(acc.y);
                acc.z = wred(acc.z); acc.w = wred(acc.w);
                if (lane == 0) {
                    psum_hh[w][0] = acc.x; psum_hh[w][1] = acc.y;
                    psum_hh[w][2] = acc.z; psum_hh[w][3] = acc.w;
                }
            }
            __syncthreads();   // (A): e staged + psum_hh ready

            // ---- phase 2: Wih * e split between the pair ----
            {
                const int jj0 = ih ? 0 : 128;
                float4 acc = make_float4(0.f, 0.f, 0.f, 0.f);
                if (valid) {
                    #pragma unroll 2
                    for (int jj = jj0 + lane; jj < jj0 + 128; jj += 32) {
                        const float4 xa = eA[jj], xb = eB[jj];
                        acc.x += dot8(wp[0][jj], xa, xb);
                        acc.y += dot8(wp[1][jj], xa, xb);
                        acc.z += dot8(wp[2][jj], xa, xb);
                        acc.w += dot8(wp[3][jj], xa, xb);
                    }
                }
                acc.x = wred(acc.x); acc.y = wred(acc.y);
                acc.z = wred(acc.z); acc.w = wred(acc.w);
                if (!ih) {
                    if (lane == 0) {
                        psum_p2[w][0] = acc.x; psum_p2[w][1] = acc.y;
                        psum_p2[w][2] = acc.z; psum_p2[w][3] = acc.w;
                    }
                } else if (lane == 0) {
                    psum_hh[w][0] += acc.x; psum_hh[w][1] += acc.y;  // hh done writing
                    psum_hh[w][2] += acc.z; psum_hh[w][3] += acc.w;
                }
            }
            __syncthreads();   // (B)

            if (ih && lane == 0 && valid) {
                const float gi = psum_hh[w][0] + psum_p2[w][0] + bsum[0];
                const float gf = psum_hh[w][1] + psum_p2[w][1] + bsum[1];
                const float gg = psum_hh[w][2] + psum_p2[w][2] + bsum[2];
                const float go = psum_hh[w][3] + psum_p2[w][3] + bsum[3];
                const float c2 = sigf(gf) * cloc + sigf(gi) * tanhf(gg);
                const float h2 = sigf(go) * tanhf(c2);
                cloc = c2;
                g_hbuf[cell & 1][gw] = h2;
                if (cell == 2 * NBK - 2) g_cbuf[gw] = c2;
            }
        }
        gen++;
        grid_sync_flags(gen);
    }

    // ---- epilogue: decode h_22 (buf 0) for the output idx ----
    if (tid < H4) {
        const float4 v = __ldcv((const float4*)g_hbuf[0] + tid);
        const int j = tid >> 1;
        if (tid & 1) hB[j] = v; else hA[j] = v;
    }
    __syncthreads();
    if (ih) {
        const float* dec; int ncls;
        dec_params(2 * NBK - 2, dec_act, dec_block, &dec, &ncls);
        if (w < ncls) {
            const float4* dr = (const float4*)(dec + (size_t)w * H);
            float s = 0.f;
            #pragma unroll 2
            for (int t2 = lane; t2 < 256; t2 += 32) {
                const float4 d0 = dr[2 * t2], d1 = dr[2 * t2 + 1];
                const float4 ha = hA[t2], hb = hB[t2];
                s += d0.x*ha.x + d0.y*ha.y + d0.z*ha.z + d0.w*ha.w
                   + d1.x*hb.x + d1.y*hb.y + d1.z*hb.z + d1.w*hb.w;
            }
            s = wred(s);
            if (lane == 0) dec_sm[w] = s;
        }
        IH_BAR();
        if (wid == 0 && lane == 0) {
            float best = dec_sm[0]; int bi = 0;
            for (int j = 1; j < ncls; j++) { float v = dec_sm[j]; if (v > best) { best = v; bi = j; } }
            idx_final = bi;
        }
    }
    // stage final c into eA/eB
    if (tid < H4) {
        const float4 v = __ldcv((const float4*)g_cbuf + tid);
        const int j = tid >> 1;
        if (tid & 1) eB[j] = v; else eA[j] = v;
    }
    __syncthreads();

    // ---- replicate outputs to all 1024 (identical) batch rows ----
    if (blockIdx.x == 0) {
        const float idxf = (float)idx_final;
        for (int i = tid; i < BSZ; i += NTHR) out[i] = idxf;
    }
    float4* outh = (float4*)(out + BSZ);
    float4* outc = (float4*)(out + BSZ + (size_t)BSZ * H);
    for (int r = blockIdx.x; r < BSZ; r += NCTA) {
        const size_t ro = (size_t)r * H4;
        for (int i = tid; i < H4; i += NTHR) {
            const int j = i >> 1;
            outh[ro + i] = (i & 1) ? hB[j] : hA[j];
            outc[ro + i] = (i & 1) ? eB[j] : eA[j];
        }
    }
}

extern "C" void kernel_launch(void* const* d_in, const int* in_sizes, int n_in,
                              void* d_out, int out_size) {
    // metadata order: inputs, W_ih, W_hh, b_ih, b_hh, enc_act, enc_block, dec_act, dec_block
    const float* W_ih      = (const float*)d_in[1];
    const float* W_hh      = (const float*)d_in[2];
    const float* b_ih      = (const float*)d_in[3];
    const float* b_hh      = (const float*)d_in[4];
    const float* enc_act   = (const float*)d_in[5];
    const float* enc_block = (const float*)d_in[6];
    const float* dec_act   = (const float*)d_in[7];
    const float* dec_block = (const float*)d_in[8];
    float* out = (float*)d_out;

    convert_weights<<<2048, 256>>>(W_ih, W_hh);
    controller_main<<<NCTA, NTHR>>>(b_ih, b_hh, enc_act, enc_block,
                                    dec_act, dec_block, out);
}

// round 10
// speedup vs baseline: 1.0031x; 1.0031x over previous
#include <cuda_runtime.h>
#include <cuda_fp16.h>
#include <math.h>

// ---------------------------------------------------------------------------
// ControllerLSTM on GB300, round 8.
// Round 7 design (128x1024 warp-specialized persistent kernel + 192KB smem
// weight cache + one-hop grid barrier) with the replay bug fixed:
// the one-hop barrier's monotonic flags persist across graph replays, so
// convert_weights now zeroes them at the start of every launch. Also removed
// the (banned) static host guard around cudaFuncSetAttribute.
// ---------------------------------------------------------------------------

#define H    2048
#define H2X  4096
#define H4   512          // float4 count of H
#define BSZ  1024
#define NBK  12

#define NCTA  128
#define NTHR  1024
#define NPAIR 16          // warp pairs per CTA; 128*16 = 2048 columns exactly

#define CJ    192         // cached uint4 per gate row (96 ih + 96 hh)
#define CPW   (4*CJ)      // cached uint4 per pair (768)
#define CTOT  (NPAIR*CPW) // per CTA (12288 uint4 = 192 KB)

__device__ __half g_wc[(size_t)4 * H * H2X];   // 67.1 MB fused fp16 weights
__device__ float  g_hbuf[2][H];
__device__ float  g_cbuf[H];

#define FLAG_STRIDE 8
__device__ volatile unsigned g_arrive[NCTA * FLAG_STRIDE];

// one-hop barrier: thread i (<NCTA) polls CTA i's flag; syncthreads combines.
// Flags are zeroed by convert_weights at the start of every launch, so the
// monotonic >= comparison is correct on every graph replay.
__device__ __forceinline__ void grid_sync_flags(unsigned gen) {
    __syncthreads();
    if (threadIdx.x == 0) {
        __threadfence();
        g_arrive[blockIdx.x * FLAG_STRIDE] = gen;
    }
    if (threadIdx.x < NCTA) {
        while (g_arrive[threadIdx.x * FLAG_STRIDE] < gen) { }
    }
    __syncthreads();
}

__device__ __forceinline__ float wred(float v) {
    #pragma unroll
    for (int o = 16; o > 0; o >>= 1) v += __shfl_xor_sync(0xffffffffu, v, o);
    return v;
}

__device__ __forceinline__ float sigf(float x) { return 1.0f / (1.0f + expf(-x)); }

__device__ __forceinline__ float dot8(uint4 w, float4 xa, float4 xb) {
    union { unsigned u; __half2 h; } c0, c1, c2, c3;
    c0.u = w.x; c1.u = w.y; c2.u = w.z; c3.u = w.w;
    const float2 f0 = __half22float2(c0.h);
    const float2 f1 = __half22float2(c1.h);
    const float2 f2 = __half22float2(c2.h);
    const float2 f3 = __half22float2(c3.h);
    return f0.x*xa.x + f0.y*xa.y + f1.x*xa.z + f1.y*xa.w
         + f2.x*xb.x + f2.y*xb.y + f3.x*xb.z + f3.y*xb.w;
}

#define IH_BAR() asm volatile("bar.sync 1, 512;" ::: "memory")

// decode params for hidden state produced by cell s
__device__ __forceinline__ void dec_params(int s, const float* dec_act,
                                           const float* dec_block,
                                           const float** dec, int* ncls) {
    if (s == 0) { *dec = dec_act; *ncls = 4; }
    else if (s & 1) { int bid = (s + 1) >> 1; *dec = dec_block + (size_t)(bid - 1) * (NBK - 1) * H; *ncls = bid; }
    else            { int bid = s >> 1;       *dec = dec_act   + (size_t)bid * 4 * H;               *ncls = 4; }
}

// ===========================================================================
// Kernel 0: fused fp16 conversion (k<2048 = W_ih row, k>=2048 = W_hh row).
// Also zeroes the barrier flags (replay safety).
// ===========================================================================
__global__ __launch_bounds__(256, 2)
void convert_weights(const float* __restrict__ W_ih, const float* __restrict__ W_hh)
{
    if (blockIdx.x == 0 && threadIdx.x < NCTA * FLAG_STRIDE)
        g_arrive[threadIdx.x] = 0;

    const size_t n = (size_t)4 * H * H2X / 8;
    const size_t stride = (size_t)gridDim.x * blockDim.x;
    uint4* __restrict__ dst = (uint4*)g_wc;
    for (size_t i = blockIdx.x * blockDim.x + threadIdx.x; i < n; i += stride) {
        const size_t o   = i * 8;
        const size_t row = o >> 12;
        const size_t k0  = o & 4095;
        const float* src = (k0 < H) ? (W_ih + row * H + k0) : (W_hh + row * H + (k0 - H));
        const float4 v0 = *(const float4*)src;
        const float4 v1 = *(const float4*)(src + 4);
        union { __half2 h; unsigned u; } a, b, c, d;
        a.h = __floats2half2_rn(v0.x, v0.y);
        b.h = __floats2half2_rn(v0.z, v0.w);
        c.h = __floats2half2_rn(v1.x, v1.y);
        d.h = __floats2half2_rn(v1.z, v1.w);
        dst[i] = make_uint4(a.u, b.u, c.u, d.u);
    }
}

// ===========================================================================
// Kernel 1: persistent controller, warp-specialized, smem weight cache.
// ===========================================================================
__global__ __launch_bounds__(NTHR, 1)
void controller_main(const float* __restrict__ b_ih,
                     const float* __restrict__ b_hh,
                     const float* __restrict__ enc_act,
                     const float* __restrict__ enc_block,
                     const float* __restrict__ dec_act,
                     const float* __restrict__ dec_block,
                     float* __restrict__ out)
{
    extern __shared__ uint4 wcache[];       // 192 KB dynamic weight cache

    __shared__ float4 hA[256], hB[256];     // h split even/odd (conflict-free)
    __shared__ float4 eA[256], eB[256];     // e (and final c in epilogue)
    __shared__ float  dec_sm[NBK - 1];
    __shared__ float  psum_hh[NPAIR][4];
    __shared__ float  psum_p2[NPAIR][4];
    __shared__ int    idx_final;

    const int tid  = threadIdx.x;
    const int lane = tid & 31;
    const int wid  = tid >> 5;
    const bool ih  = (wid < NPAIR);             // threads 0..511
    const int w    = wid & (NPAIR - 1);
    const int gw   = blockIdx.x * NPAIR + w;    // gate column (always < 2048)

    float bsum[4];
    #pragma unroll
    for (int g = 0; g < 4; g++) bsum[g] = b_ih[g * H + gw] + b_hh[g * H + gw];

    const uint4* wp[4];
    #pragma unroll
    for (int g = 0; g < 4; g++)
        wp[g] = ((const uint4*)g_wc) + (size_t)(g * H + gw) * 512;

    // ---- fill weight cache: per pair, per gate: c<96 -> ih j=c, else hh j=256+c-96
    for (int i = tid; i < CTOT; i += NTHR) {
        const int p = i / CPW, rem = i - p * CPW;
        const int g = rem / CJ, c = rem - g * CJ;
        const int j = (c < 96) ? c : (256 + c - 96);
        wcache[i] = ((const uint4*)g_wc)[(size_t)(g * H + blockIdx.x * NPAIR + p) * 512 + j];
    }
    __syncthreads();
    const uint4* wc = wcache + w * CPW;         // this pair's cache

    float cloc = 0.f;          // ih lane 0 of each pair
    unsigned gen = 0;

    for (int cell = 0; cell < 2 * NBK - 1; cell++) {
        if (cell == 0) {
            // x=0, h=0 -> gates are pure biases
            if (ih && lane == 0) {
                const float c2 = sigf(bsum[0]) * tanhf(bsum[2]);
                const float h2 = sigf(bsum[3]) * tanhf(c2);
                cloc = c2;
                g_hbuf[0][gw] = h2;
            }
        } else {
            // ---- stage h_{cell-1} into split arrays ----
            if (tid < H4) {
                const float4 v = __ldcv((const float4*)g_hbuf[(cell - 1) & 1] + tid);
                const int j = tid >> 1;
                if (tid & 1) hB[j] = v; else hA[j] = v;
            }
            __syncthreads();

            if (ih) {
                // ---- phase 1 (ih): decode h_{cell-1}, stage e_cell ----
                const float* dec; int ncls;
                dec_params(cell - 1, dec_act, dec_block, &dec, &ncls);
                if (w < ncls) {
                    const float4* dr = (const float4*)(dec + (size_t)w * H);
                    float s = 0.f;
                    #pragma unroll 2
                    for (int t2 = lane; t2 < 256; t2 += 32) {
                        const float4 d0 = dr[2 * t2], d1 = dr[2 * t2 + 1];
                        const float4 ha = hA[t2], hb = hB[t2];
                        s += d0.x*ha.x + d0.y*ha.y + d0.z*ha.z + d0.w*ha.w
                           + d1.x*hb.x + d1.y*hb.y + d1.z*hb.z + d1.w*hb.w;
                    }
                    s = wred(s);
                    if (lane == 0) dec_sm[w] = s;
                }
                IH_BAR();
                float best = dec_sm[0]; int bi = 0;
                for (int j = 1; j < ncls; j++) { float v = dec_sm[j]; if (v > best) { best = v; bi = j; } }
                const int bid = (cell + 1) >> 1;
                const float* emb = (cell & 1)
                    ? enc_act   + ((size_t)(bid - 1) * 4         + bi) * H
                    : enc_block + ((size_t)(bid - 1) * (NBK - 1) + bi) * H;
                {   // tid in [0,512): one float4 each
                    const float4 v = __ldg((const float4*)emb + tid);
                    const int j = tid >> 1;
                    if (tid & 1) eB[j] = v; else eA[j] = v;
                }
            } else {
                // ---- phase 1 (hh): Whh*h. jj in [0,96) cached, [96,256) global ----
                float4 acc = make_float4(0.f, 0.f, 0.f, 0.f);
                #pragma unroll
                for (int k = 0; k < 3; k++) {
                    const int jj = lane + 32 * k;
                    const float4 xa = hA[jj], xb = hB[jj];
                    acc.x += dot8(wc[0 * CJ + 96 + jj], xa, xb);
                    acc.y += dot8(wc[1 * CJ + 96 + jj], xa, xb);
                    acc.z += dot8(wc[2 * CJ + 96 + jj], xa, xb);
                    acc.w += dot8(wc[3 * CJ + 96 + jj], xa, xb);
                }
                #pragma unroll
                for (int k = 3; k < 8; k++) {
                    const int jj = lane + 32 * k;
                    const float4 xa = hA[jj], xb = hB[jj];
                    acc.x += dot8(wp[0][256 + jj], xa, xb);
                    acc.y += dot8(wp[1][256 + jj], xa, xb);
                    acc.z += dot8(wp[2][256 + jj], xa, xb);
                    acc.w += dot8(wp[3][256 + jj], xa, xb);
                }
                acc.x = wred(acc.x); acc.y = wred(acc.y);
                acc.z = wred(acc.z); acc.w = wred(acc.w);
                if (lane == 0) {
                    psum_hh[w][0] = acc.x; psum_hh[w][1] = acc.y;
                    psum_hh[w][2] = acc.z; psum_hh[w][3] = acc.w;
                }
            }
            __syncthreads();   // (A): e staged + psum_hh ready

            // ---- phase 2: Wih*e. ih warp: [0,96) smem + [96,160) glob;
            //               hh warp: [160,256) glob ----
            {
                float4 acc = make_float4(0.f, 0.f, 0.f, 0.f);
                if (ih) {
                    #pragma unroll
                    for (int k = 0; k < 3; k++) {
                        const int jj = lane + 32 * k;
                        const float4 xa = eA[jj], xb = eB[jj];
                        acc.x += dot8(wc[0 * CJ + jj], xa, xb);
                        acc.y += dot8(wc[1 * CJ + jj], xa, xb);
                        acc.z += dot8(wc[2 * CJ + jj], xa, xb);
                        acc.w += dot8(wc[3 * CJ + jj], xa, xb);
                    }
                    #pragma unroll
                    for (int k = 3; k < 5; k++) {
                        const int jj = lane + 32 * k;
                        const float4 xa = eA[jj], xb = eB[jj];
                        acc.x += dot8(wp[0][jj], xa, xb);
                        acc.y += dot8(wp[1][jj], xa, xb);
                        acc.z += dot8(wp[2][jj], xa, xb);
                        acc.w += dot8(wp[3][jj], xa, xb);
                    }
                } else {
                    #pragma unroll
                    for (int k = 5; k < 8; k++) {
                        const int jj = lane + 32 * k;
                        const float4 xa = eA[jj], xb = eB[jj];
                        acc.x += dot8(wp[0][jj], xa, xb);
                        acc.y += dot8(wp[1][jj], xa, xb);
                        acc.z += dot8(wp[2][jj], xa, xb);
                        acc.w += dot8(wp[3][jj], xa, xb);
                    }
                }
                acc.x = wred(acc.x); acc.y = wred(acc.y);
                acc.z = wred(acc.z); acc.w = wred(acc.w);
                if (!ih) {
                    if (lane == 0) {
                        psum_p2[w][0] = acc.x; psum_p2[w][1] = acc.y;
                        psum_p2[w][2] = acc.z; psum_p2[w][3] = acc.w;
                    }
                } else if (lane == 0) {
                    psum_hh[w][0] += acc.x; psum_hh[w][1] += acc.y;  // hh done writing
                    psum_hh[w][2] += acc.z; psum_hh[w][3] += acc.w;
                }
            }
            __syncthreads();   // (B)

            if (ih && lane == 0) {
                const float gi = psum_hh[w][0] + psum_p2[w][0] + bsum[0];
                const float gf = psum_hh[w][1] + psum_p2[w][1] + bsum[1];
                const float gg = psum_hh[w][2] + psum_p2[w][2] + bsum[2];
                const float go = psum_hh[w][3] + psum_p2[w][3] + bsum[3];
                const float c2 = sigf(gf) * cloc + sigf(gi) * tanhf(gg);
                const float h2 = sigf(go) * tanhf(c2);
                cloc = c2;
                g_hbuf[cell & 1][gw] = h2;
                if (cell == 2 * NBK - 2) g_cbuf[gw] = c2;
            }
        }
        gen++;
        grid_sync_flags(gen);
    }

    // ---- epilogue: decode h_22 (buf 0) for the output idx ----
    if (tid < H4) {
        const float4 v = __ldcv((const float4*)g_hbuf[0] + tid);
        const int j = tid >> 1;
        if (tid & 1) hB[j] = v; else hA[j] = v;
    }
    __syncthreads();
    if (ih) {
        const float* dec; int ncls;
        dec_params(2 * NBK - 2, dec_act, dec_block, &dec, &ncls);
        if (w < ncls) {
            const float4* dr = (const float4*)(dec + (size_t)w * H);
            float s = 0.f;
            #pragma unroll 2
            for (int t2 = lane; t2 < 256; t2 += 32) {
                const float4 d0 = dr[2 * t2], d1 = dr[2 * t2 + 1];
                const float4 ha = hA[t2], hb = hB[t2];
                s += d0.x*ha.x + d0.y*ha.y + d0.z*ha.z + d0.w*ha.w
                   + d1.x*hb.x + d1.y*hb.y + d1.z*hb.z + d1.w*hb.w;
            }
            s = wred(s);
            if (lane == 0) dec_sm[w] = s;
        }
        IH_BAR();
        if (wid == 0 && lane == 0) {
            float best = dec_sm[0]; int bi = 0;
            for (int j = 1; j < ncls; j++) { float v = dec_sm[j]; if (v > best) { best = v; bi = j; } }
            idx_final = bi;
        }
    }
    // stage final c into eA/eB
    if (tid < H4) {
        const float4 v = __ldcv((const float4*)g_cbuf + tid);
        const int j = tid >> 1;
        if (tid & 1) eB[j] = v; else eA[j] = v;
    }
    __syncthreads();

    // ---- replicate outputs to all 1024 (identical) batch rows ----
    if (blockIdx.x == 0) {
        const float idxf = (float)idx_final;
        for (int i = tid; i < BSZ; i += NTHR) out[i] = idxf;
    }
    float4* outh = (float4*)(out + BSZ);
    float4* outc = (float4*)(out + BSZ + (size_t)BSZ * H);
    for (int r = blockIdx.x; r < BSZ; r += NCTA) {
        const size_t ro = (size_t)r * H4;
        for (int i = tid; i < H4; i += NTHR) {
            const int j = i >> 1;
            outh[ro + i] = (i & 1) ? hB[j] : hA[j];
            outc[ro + i] = (i & 1) ? eB[j] : eA[j];
        }
    }
}

extern "C" void kernel_launch(void* const* d_in, const int* in_sizes, int n_in,
                              void* d_out, int out_size) {
    // metadata order: inputs, W_ih, W_hh, b_ih, b_hh, enc_act, enc_block, dec_act, dec_block
    const float* W_ih      = (const float*)d_in[1];
    const float* W_hh      = (const float*)d_in[2];
    const float* b_ih      = (const float*)d_in[3];
    const float* b_hh      = (const float*)d_in[4];
    const float* enc_act   = (const float*)d_in[5];
    const float* enc_block = (const float*)d_in[6];
    const float* dec_act   = (const float*)d_in[7];
    const float* dec_block = (const float*)d_in[8];
    float* out = (float*)d_out;

    cudaFuncSetAttribute(controller_main,
                         cudaFuncAttributeMaxDynamicSharedMemorySize,
                         CTOT * sizeof(uint4));

    convert_weights<<<2048, 256>>>(W_ih, W_hh);
    controller_main<<<NCTA, NTHR, CTOT * sizeof(uint4)>>>(
        b_ih, b_hh, enc_act, enc_block, dec_act, dec_block, out);
}